// round 2
// baseline (speedup 1.0000x reference)
#include <cuda_runtime.h>
#include <cstddef>

#define SEQ 4096
#define DIM 1024
#define NHEAD 16
#define HDIM 64

// Scratch (no allocations allowed)
__device__ float g_qkv[(size_t)SEQ * 3 * DIM];   // [T, 3D]
__device__ float g_y[(size_t)SEQ * DIM];         // [T, D] attention output

// ---------------------------------------------------------------------------
// SGEMM "NT": C[m][n] = sum_k A[m][k] * B[n][k]
// A: [M,K] row-major, B: [N,K] row-major (torch Linear weight layout), C: [M,N]
// 128x128 block tile, KT=16, 256 threads, 8x8 per-thread micro tile.
// Requires M%128==0, N%128==0, K%16==0.
// ---------------------------------------------------------------------------
__global__ __launch_bounds__(256) void sgemm_nt(const float* __restrict__ A,
                                                const float* __restrict__ B,
                                                float* __restrict__ C,
                                                int M, int N, int K)
{
    __shared__ __align__(16) float As[16][128];
    __shared__ __align__(16) float Bs[16][128];

    const int tid = threadIdx.x;
    const int tx = tid & 15;        // 0..15 -> n micro tile
    const int ty = tid >> 4;        // 0..15 -> m micro tile
    const int bm = blockIdx.y * 128;
    const int bn = blockIdx.x * 128;

    float acc[8][8];
#pragma unroll
    for (int i = 0; i < 8; ++i)
#pragma unroll
        for (int j = 0; j < 8; ++j) acc[i][j] = 0.f;

    for (int k0 = 0; k0 < K; k0 += 16) {
        // Load tiles (transposed into smem: As[k][m], Bs[k][n])
#pragma unroll
        for (int t = 0; t < 2; ++t) {
            int idx = tid + t * 256;          // 0..511
            int r = idx >> 2;                 // 0..127
            int c4 = idx & 3;                 // 0..3 (float4 within k-slab)
            float4 va = *(const float4*)&A[(size_t)(bm + r) * K + k0 + c4 * 4];
            As[c4 * 4 + 0][r] = va.x;
            As[c4 * 4 + 1][r] = va.y;
            As[c4 * 4 + 2][r] = va.z;
            As[c4 * 4 + 3][r] = va.w;
            float4 vb = *(const float4*)&B[(size_t)(bn + r) * K + k0 + c4 * 4];
            Bs[c4 * 4 + 0][r] = vb.x;
            Bs[c4 * 4 + 1][r] = vb.y;
            Bs[c4 * 4 + 2][r] = vb.z;
            Bs[c4 * 4 + 3][r] = vb.w;
        }
        __syncthreads();

#pragma unroll
        for (int k = 0; k < 16; ++k) {
            float4 a0 = *(const float4*)&As[k][ty * 8];
            float4 a1 = *(const float4*)&As[k][ty * 8 + 4];
            float4 b0 = *(const float4*)&Bs[k][tx * 8];
            float4 b1 = *(const float4*)&Bs[k][tx * 8 + 4];
            float a[8] = {a0.x, a0.y, a0.z, a0.w, a1.x, a1.y, a1.z, a1.w};
            float b[8] = {b0.x, b0.y, b0.z, b0.w, b1.x, b1.y, b1.z, b1.w};
#pragma unroll
            for (int i = 0; i < 8; ++i)
#pragma unroll
                for (int j = 0; j < 8; ++j) acc[i][j] = fmaf(a[i], b[j], acc[i][j]);
        }
        __syncthreads();
    }

    // Epilogue
#pragma unroll
    for (int i = 0; i < 8; ++i) {
        float* crow = &C[(size_t)(bm + ty * 8 + i) * N + bn + tx * 8];
        float4 v0 = make_float4(acc[i][0], acc[i][1], acc[i][2], acc[i][3]);
        float4 v1 = make_float4(acc[i][4], acc[i][5], acc[i][6], acc[i][7]);
        *(float4*)&crow[0] = v0;
        *(float4*)&crow[4] = v1;
    }
}

// ---------------------------------------------------------------------------
// Flash attention, fp32, causal. One block per (query tile of 64, head).
// 256 threads as 16x16; each thread owns 4 rows x 4 cols micro tiles for both
// S = Q K^T (64x64) and O accumulation (rows x head-dim slice).
// smem: Qt[d][m], KPt (K^T then reused for P^T), Vs[n][d]. 3*16KB = 48KB.
// ---------------------------------------------------------------------------
__global__ __launch_bounds__(256) void attn_kernel(const float* __restrict__ qkv,
                                                   float* __restrict__ y)
{
    __shared__ __align__(16) float Qt[64][64];   // Qt[d][m]
    __shared__ __align__(16) float KPt[64][64];  // Kt[d][n] then Pt[n][m]
    __shared__ __align__(16) float Vs[64][64];   // Vs[n][d]

    const int tid = threadIdx.x;
    const int tx = tid & 15;
    const int ty = tid >> 4;
    const int qb = blockIdx.x;   // query tile 0..63
    const int h  = blockIdx.y;   // head 0..15
    const float scale = 0.125f;  // 1/sqrt(64)

    const int m0 = ty * 4;       // local query rows
    const int n0 = tx * 4;       // local key cols / head-dim cols

    // Load Q tile transposed: Qt[d][m]
    for (int i = tid; i < 64 * 16; i += 256) {
        int r = i >> 4;          // query row 0..63
        int c4 = i & 15;         // float4 index along d
        float4 v = *(const float4*)&qkv[(size_t)(qb * 64 + r) * (3 * DIM) + h * HDIM + c4 * 4];
        Qt[c4 * 4 + 0][r] = v.x;
        Qt[c4 * 4 + 1][r] = v.y;
        Qt[c4 * 4 + 2][r] = v.z;
        Qt[c4 * 4 + 3][r] = v.w;
    }

    float o[4][4];
    float m_i[4], l_i[4];
#pragma unroll
    for (int i = 0; i < 4; ++i) {
        m_i[i] = -1e30f;
        l_i[i] = 0.f;
#pragma unroll
        for (int j = 0; j < 4; ++j) o[i][j] = 0.f;
    }

    for (int kt = 0; kt <= qb; ++kt) {
        __syncthreads();  // previous-iter reads of KPt/Vs done; Qt visible on iter 0

        // Load K tile transposed + V tile
        for (int i = tid; i < 64 * 16; i += 256) {
            int r = i >> 4;      // key row 0..63
            int c4 = i & 15;
            size_t base = (size_t)(kt * 64 + r) * (3 * DIM) + h * HDIM + c4 * 4;
            float4 kv = *(const float4*)&qkv[base + DIM];
            KPt[c4 * 4 + 0][r] = kv.x;
            KPt[c4 * 4 + 1][r] = kv.y;
            KPt[c4 * 4 + 2][r] = kv.z;
            KPt[c4 * 4 + 3][r] = kv.w;
            float4 vv = *(const float4*)&qkv[base + 2 * DIM];
            *(float4*)&Vs[r][c4 * 4] = vv;
        }
        __syncthreads();

        // S = Q K^T (4x4 micro tile per thread)
        float p[4][4];
#pragma unroll
        for (int i = 0; i < 4; ++i)
#pragma unroll
            for (int j = 0; j < 4; ++j) p[i][j] = 0.f;

#pragma unroll 8
        for (int d = 0; d < 64; ++d) {
            float4 a = *(const float4*)&Qt[d][m0];
            float4 b = *(const float4*)&KPt[d][n0];
            float av[4] = {a.x, a.y, a.z, a.w};
            float bv[4] = {b.x, b.y, b.z, b.w};
#pragma unroll
            for (int i = 0; i < 4; ++i)
#pragma unroll
                for (int j = 0; j < 4; ++j) p[i][j] = fmaf(av[i], bv[j], p[i][j]);
        }

        const bool diag = (kt == qb);
#pragma unroll
        for (int i = 0; i < 4; ++i) {
#pragma unroll
            for (int j = 0; j < 4; ++j) {
                p[i][j] *= scale;
                if (diag && (n0 + j > m0 + i)) p[i][j] = -1e30f;
            }
        }

        // Online softmax: reduce across the 16 threads sharing each row
        // (lanes with equal ty are 16 consecutive lanes; xor<=8 stays in group)
#pragma unroll
        for (int i = 0; i < 4; ++i) {
            float mx = fmaxf(fmaxf(p[i][0], p[i][1]), fmaxf(p[i][2], p[i][3]));
#pragma unroll
            for (int off = 8; off >= 1; off >>= 1)
                mx = fmaxf(mx, __shfl_xor_sync(0xffffffffu, mx, off));
            float mnew = fmaxf(m_i[i], mx);
            float lsum = 0.f;
#pragma unroll
            for (int j = 0; j < 4; ++j) {
                p[i][j] = __expf(p[i][j] - mnew);
                lsum += p[i][j];
            }
#pragma unroll
            for (int off = 8; off >= 1; off >>= 1)
                lsum += __shfl_xor_sync(0xffffffffu, lsum, off);
            float alpha = __expf(m_i[i] - mnew);
            l_i[i] = l_i[i] * alpha + lsum;
            m_i[i] = mnew;
#pragma unroll
            for (int j = 0; j < 4; ++j) o[i][j] *= alpha;
        }

        __syncthreads();  // everyone done reading KPt as K^T

        // Write P^T into KPt: Pt[n][m]
#pragma unroll
        for (int i = 0; i < 4; ++i)
#pragma unroll
            for (int j = 0; j < 4; ++j) KPt[n0 + j][m0 + i] = p[i][j];
        __syncthreads();

        // O += P V   (o[i][j]: row m0+i, dim n0+j)
#pragma unroll 8
        for (int n = 0; n < 64; ++n) {
            float4 a = *(const float4*)&KPt[n][m0];
            float4 b = *(const float4*)&Vs[n][n0];
            float av[4] = {a.x, a.y, a.z, a.w};
            float bv[4] = {b.x, b.y, b.z, b.w};
#pragma unroll
            for (int i = 0; i < 4; ++i)
#pragma unroll
                for (int j = 0; j < 4; ++j) o[i][j] = fmaf(av[i], bv[j], o[i][j]);
        }
    }

    // Normalize and write: y[t][h*64 + d]
#pragma unroll
    for (int i = 0; i < 4; ++i) {
        float inv = 1.f / l_i[i];
        float4 v = make_float4(o[i][0] * inv, o[i][1] * inv, o[i][2] * inv, o[i][3] * inv);
        *(float4*)&y[(size_t)(qb * 64 + m0 + i) * DIM + h * HDIM + n0] = v;
    }
}

// ---------------------------------------------------------------------------
extern "C" void kernel_launch(void* const* d_in, const int* in_sizes, int n_in,
                              void* d_out, int out_size)
{
    (void)in_sizes; (void)n_in; (void)out_size;
    const float* x      = (const float*)d_in[0];   // [1,4096,1024]
    const float* w_attn = (const float*)d_in[1];   // [3072,1024]
    const float* w_proj = (const float*)d_in[2];   // [1024,1024]
    float* out = (float*)d_out;                    // [1,4096,1024]

    float* qkv_p = nullptr;
    float* y_p   = nullptr;
    cudaGetSymbolAddress((void**)&qkv_p, g_qkv);
    cudaGetSymbolAddress((void**)&y_p, g_y);

    // 1) QKV projection: [4096,1024] x [3072,1024]^T -> [4096,3072]
    {
        dim3 grid(3 * DIM / 128, SEQ / 128);
        sgemm_nt<<<grid, 256>>>(x, w_attn, qkv_p, SEQ, 3 * DIM, DIM);
    }
    // 2) Causal flash attention -> g_y [4096,1024]
    {
        dim3 grid(SEQ / 64, NHEAD);
        attn_kernel<<<grid, 256>>>(qkv_p, y_p);
    }
    // 3) Output projection: [4096,1024] x [1024,1024]^T -> out
    {
        dim3 grid(DIM / 128, SEQ / 128);
        sgemm_nt<<<grid, 256>>>(y_p, w_proj, out, SEQ, DIM, DIM);
    }
}

// round 6
// speedup vs baseline: 3.7167x; 3.7167x over previous
#include <cuda_runtime.h>
#include <cstddef>

#define SEQ 4096
#define DIM 1024
#define NHEAD 16
#define HDIM 64

__device__ float g_qkv[(size_t)SEQ * 3 * DIM];   // [T, 3D]
__device__ float g_y[(size_t)SEQ * DIM];         // [T, D]

__device__ __forceinline__ unsigned f2tf(float f) {
    unsigned u;
    asm("cvt.rna.tf32.f32 %0, %1;" : "=r"(u) : "f"(f));
    return u;
}

__device__ __forceinline__ void mma_tf32(float c[4], const unsigned a[4], const unsigned b[2]) {
    asm volatile(
        "mma.sync.aligned.m16n8k8.row.col.f32.tf32.tf32.f32 "
        "{%0,%1,%2,%3}, {%4,%5,%6,%7}, {%8,%9}, {%0,%1,%2,%3};"
        : "+f"(c[0]), "+f"(c[1]), "+f"(c[2]), "+f"(c[3])
        : "r"(a[0]), "r"(a[1]), "r"(a[2]), "r"(a[3]), "r"(b[0]), "r"(b[1]));
}

// ---------------------------------------------------------------------------
// TF32 GEMM "NT": C[m][n] = sum_k A[m][k] * B[n][k]
// 128x128 block tile, KT=32, 256 threads = 8 warps (2m x 4n), warp tile 64x32.
// Smem [row][k] with stride 36 (pad 4): conflict-free frag loads, aligned STS.128.
// ---------------------------------------------------------------------------
#define GKT 32
__global__ __launch_bounds__(256) void gemm_tf32_nt(const float* __restrict__ A,
                                                    const float* __restrict__ B,
                                                    float* __restrict__ C,
                                                    int M, int N, int K)
{
    __shared__ unsigned As[128][36];
    __shared__ unsigned Bs[128][36];

    const int tid  = threadIdx.x;
    const int lane = tid & 31;
    const int warp = tid >> 5;
    const int wm = warp & 1;        // 0..1
    const int wn = warp >> 1;       // 0..3
    const int bm = blockIdx.y * 128;
    const int bn = blockIdx.x * 128;
    const int g = lane >> 2;        // 0..7
    const int r = lane & 3;         // 0..3

    float acc[4][4][4];
#pragma unroll
    for (int mi = 0; mi < 4; ++mi)
#pragma unroll
        for (int nj = 0; nj < 4; ++nj)
#pragma unroll
            for (int e = 0; e < 4; ++e) acc[mi][nj][e] = 0.f;

    for (int k0 = 0; k0 < K; k0 += GKT) {
        // Stage A,B tiles (convert to tf32 bits). 128 rows x 32 k = 1024 float4.
#pragma unroll
        for (int t = 0; t < 4; ++t) {
            int idx = tid + t * 256;
            int row = idx >> 3;
            int c4  = idx & 7;
            float4 va = *(const float4*)&A[(size_t)(bm + row) * K + k0 + c4 * 4];
            *(uint4*)&As[row][c4 * 4] = make_uint4(f2tf(va.x), f2tf(va.y), f2tf(va.z), f2tf(va.w));
            float4 vb = *(const float4*)&B[(size_t)(bn + row) * K + k0 + c4 * 4];
            *(uint4*)&Bs[row][c4 * 4] = make_uint4(f2tf(vb.x), f2tf(vb.y), f2tf(vb.z), f2tf(vb.w));
        }
        __syncthreads();

#pragma unroll
        for (int kk = 0; kk < 4; ++kk) {
            const int c = kk * 8 + r;
            unsigned af[4][4];
#pragma unroll
            for (int mi = 0; mi < 4; ++mi) {
                int row = wm * 64 + mi * 16 + g;
                af[mi][0] = As[row][c];
                af[mi][1] = As[row + 8][c];
                af[mi][2] = As[row][c + 4];
                af[mi][3] = As[row + 8][c + 4];
            }
            unsigned bf[4][2];
#pragma unroll
            for (int nj = 0; nj < 4; ++nj) {
                int col = wn * 32 + nj * 8 + g;
                bf[nj][0] = Bs[col][c];
                bf[nj][1] = Bs[col][c + 4];
            }
#pragma unroll
            for (int mi = 0; mi < 4; ++mi)
#pragma unroll
                for (int nj = 0; nj < 4; ++nj)
                    mma_tf32(acc[mi][nj], af[mi], bf[nj]);
        }
        __syncthreads();
    }

    // Epilogue
#pragma unroll
    for (int mi = 0; mi < 4; ++mi) {
        int m = bm + wm * 64 + mi * 16 + g;
#pragma unroll
        for (int nj = 0; nj < 4; ++nj) {
            int n = bn + wn * 32 + nj * 8 + 2 * r;
            *(float2*)&C[(size_t)m * N + n]       = make_float2(acc[mi][nj][0], acc[mi][nj][1]);
            *(float2*)&C[(size_t)(m + 8) * N + n] = make_float2(acc[mi][nj][2], acc[mi][nj][3]);
        }
    }
}

// ---------------------------------------------------------------------------
// TF32 flash attention, causal. Block = (64-query tile, head), 4 warps.
// Q fragments register-resident; K smem stride 68, V smem stride 72
// (conflict-free for their fragment access patterns). P stays in registers:
// S-accumulator -> A-fragment via shuffles.
// ---------------------------------------------------------------------------
__global__ __launch_bounds__(128) void attn_tf32(const float* __restrict__ qkv,
                                                 float* __restrict__ y)
{
    __shared__ unsigned Ks[64][68];   // Q staging, then K tiles
    __shared__ unsigned Vs[64][72];   // V tiles

    const int tid  = threadIdx.x;
    const int lane = tid & 31;
    const int warp = tid >> 5;
    const int qb = blockIdx.x;
    const int h  = blockIdx.y;
    const int g = lane >> 2;
    const int r = lane & 3;
    const int row0 = warp * 16;       // this warp's 16 rows within the 64-tile

    // ---- Stage Q (tf32) into Ks, then pull fragments into registers ----
#pragma unroll
    for (int t = 0; t < 8; ++t) {
        int idx = tid + t * 128;
        int row = idx >> 4;
        int c4  = idx & 15;
        float4 v = *(const float4*)&qkv[(size_t)(qb * 64 + row) * (3 * DIM) + h * HDIM + c4 * 4];
        *(uint4*)&Ks[row][c4 * 4] = make_uint4(f2tf(v.x), f2tf(v.y), f2tf(v.z), f2tf(v.w));
    }
    __syncthreads();

    unsigned qf[8][4];
#pragma unroll
    for (int kk = 0; kk < 8; ++kk) {
        int c = kk * 8 + r;
        qf[kk][0] = Ks[row0 + g][c];
        qf[kk][1] = Ks[row0 + 8 + g][c];
        qf[kk][2] = Ks[row0 + g][c + 4];
        qf[kk][3] = Ks[row0 + 8 + g][c + 4];
    }
    __syncthreads();

    float oacc[8][4];
#pragma unroll
    for (int j = 0; j < 8; ++j)
#pragma unroll
        for (int e = 0; e < 4; ++e) oacc[j][e] = 0.f;

    float m_lo = -1e30f, m_hi = -1e30f, l_lo = 0.f, l_hi = 0.f;
    const float scale = 0.125f;

    for (int kt = 0; kt <= qb; ++kt) {
        // ---- Load K (stride 68) and V (stride 72) tiles, tf32 ----
#pragma unroll
        for (int t = 0; t < 8; ++t) {
            int idx = tid + t * 128;
            int row = idx >> 4;
            int c4  = idx & 15;
            size_t base = (size_t)(kt * 64 + row) * (3 * DIM) + h * HDIM + c4 * 4;
            float4 kv = *(const float4*)&qkv[base + DIM];
            *(uint4*)&Ks[row][c4 * 4] = make_uint4(f2tf(kv.x), f2tf(kv.y), f2tf(kv.z), f2tf(kv.w));
            float4 vv = *(const float4*)&qkv[base + 2 * DIM];
            *(uint4*)&Vs[row][c4 * 4] = make_uint4(f2tf(vv.x), f2tf(vv.y), f2tf(vv.z), f2tf(vv.w));
        }
        __syncthreads();

        // ---- S = Q K^T : 8 n-tiles x 8 k-steps of mma ----
        float s[8][4];
#pragma unroll
        for (int j = 0; j < 8; ++j)
#pragma unroll
            for (int e = 0; e < 4; ++e) s[j][e] = 0.f;

#pragma unroll
        for (int kk = 0; kk < 8; ++kk) {
            const int c = kk * 8 + r;
            unsigned bK[8][2];
#pragma unroll
            for (int j = 0; j < 8; ++j) {
                int key = j * 8 + g;
                bK[j][0] = Ks[key][c];
                bK[j][1] = Ks[key][c + 4];
            }
#pragma unroll
            for (int j = 0; j < 8; ++j) mma_tf32(s[j], qf[kk], bK[j]);
        }

        // ---- mask + online softmax (rows: lo = row0+g, hi = row0+8+g) ----
        const bool diag = (kt == qb);
        float mx_lo = -1e30f, mx_hi = -1e30f;
#pragma unroll
        for (int j = 0; j < 8; ++j) {
#pragma unroll
            for (int e = 0; e < 2; ++e) {
                int col = j * 8 + 2 * r + e;
                float plo = s[j][e] * scale;
                float phi = s[j][2 + e] * scale;
                if (diag && col > row0 + g) plo = -1e30f;
                if (diag && col > row0 + 8 + g) phi = -1e30f;
                s[j][e] = plo;
                s[j][2 + e] = phi;
                mx_lo = fmaxf(mx_lo, plo);
                mx_hi = fmaxf(mx_hi, phi);
            }
        }
#pragma unroll
        for (int off = 1; off <= 2; off <<= 1) {
            mx_lo = fmaxf(mx_lo, __shfl_xor_sync(0xffffffffu, mx_lo, off));
            mx_hi = fmaxf(mx_hi, __shfl_xor_sync(0xffffffffu, mx_hi, off));
        }
        float mn_lo = fmaxf(m_lo, mx_lo);
        float mn_hi = fmaxf(m_hi, mx_hi);
        float sum_lo = 0.f, sum_hi = 0.f;
#pragma unroll
        for (int j = 0; j < 8; ++j) {
#pragma unroll
            for (int e = 0; e < 2; ++e) {
                s[j][e]     = __expf(s[j][e] - mn_lo);
                s[j][2 + e] = __expf(s[j][2 + e] - mn_hi);
                sum_lo += s[j][e];
                sum_hi += s[j][2 + e];
            }
        }
#pragma unroll
        for (int off = 1; off <= 2; off <<= 1) {
            sum_lo += __shfl_xor_sync(0xffffffffu, sum_lo, off);
            sum_hi += __shfl_xor_sync(0xffffffffu, sum_hi, off);
        }
        float al_lo = __expf(m_lo - mn_lo);
        float al_hi = __expf(m_hi - mn_hi);
        l_lo = l_lo * al_lo + sum_lo;
        l_hi = l_hi * al_hi + sum_hi;
        m_lo = mn_lo;
        m_hi = mn_hi;
#pragma unroll
        for (int j = 0; j < 8; ++j) {
            oacc[j][0] *= al_lo; oacc[j][1] *= al_lo;
            oacc[j][2] *= al_hi; oacc[j][3] *= al_hi;
        }

        // ---- P to tf32 bits ----
        unsigned pt[8][4];
#pragma unroll
        for (int j = 0; j < 8; ++j)
#pragma unroll
            for (int e = 0; e < 4; ++e) pt[j][e] = f2tf(s[j][e]);

        // ---- O += P V : A-frags built from S-acc via shuffles ----
        const int srcA = (lane & ~3) | (r >> 1);
        const int srcB = (lane & ~3) | (((r + 4) >> 1));
        const bool odd = (r & 1);
#pragma unroll
        for (int kk = 0; kk < 8; ++kk) {
            unsigned a[4];
            {
                unsigned t0 = __shfl_sync(0xffffffffu, pt[kk][0], srcA);
                unsigned t1 = __shfl_sync(0xffffffffu, pt[kk][1], srcA);
                unsigned t2 = __shfl_sync(0xffffffffu, pt[kk][0], srcB);
                unsigned t3 = __shfl_sync(0xffffffffu, pt[kk][1], srcB);
                a[0] = odd ? t1 : t0;
                a[2] = odd ? t3 : t2;
                t0 = __shfl_sync(0xffffffffu, pt[kk][2], srcA);
                t1 = __shfl_sync(0xffffffffu, pt[kk][3], srcA);
                t2 = __shfl_sync(0xffffffffu, pt[kk][2], srcB);
                t3 = __shfl_sync(0xffffffffu, pt[kk][3], srcB);
                a[1] = odd ? t1 : t0;
                a[3] = odd ? t3 : t2;
            }
#pragma unroll
            for (int j = 0; j < 8; ++j) {
                unsigned bV[2];
                bV[0] = Vs[kk * 8 + r][j * 8 + g];
                bV[1] = Vs[kk * 8 + r + 4][j * 8 + g];
                mma_tf32(oacc[j], a, bV);
            }
        }
        __syncthreads();
    }

    // ---- normalize + write ----
    float inv_lo = 1.f / l_lo;
    float inv_hi = 1.f / l_hi;
    int row_lo = qb * 64 + row0 + g;
#pragma unroll
    for (int j = 0; j < 8; ++j) {
        int n = h * HDIM + j * 8 + 2 * r;
        *(float2*)&y[(size_t)row_lo * DIM + n] =
            make_float2(oacc[j][0] * inv_lo, oacc[j][1] * inv_lo);
        *(float2*)&y[(size_t)(row_lo + 8) * DIM + n] =
            make_float2(oacc[j][2] * inv_hi, oacc[j][3] * inv_hi);
    }
}

// ---------------------------------------------------------------------------
extern "C" void kernel_launch(void* const* d_in, const int* in_sizes, int n_in,
                              void* d_out, int out_size)
{
    (void)in_sizes; (void)n_in; (void)out_size;
    const float* x      = (const float*)d_in[0];
    const float* w_attn = (const float*)d_in[1];
    const float* w_proj = (const float*)d_in[2];
    float* out = (float*)d_out;

    float* qkv_p = nullptr;
    float* y_p   = nullptr;
    cudaGetSymbolAddress((void**)&qkv_p, g_qkv);
    cudaGetSymbolAddress((void**)&y_p, g_y);

    {   // QKV: [4096,1024] x [3072,1024]^T
        dim3 grid(3 * DIM / 128, SEQ / 128);
        gemm_tf32_nt<<<grid, 256>>>(x, w_attn, qkv_p, SEQ, 3 * DIM, DIM);
    }
    {   // causal flash attention
        dim3 grid(SEQ / 64, NHEAD);
        attn_tf32<<<grid, 128>>>(qkv_p, y_p);
    }
    {   // proj: [4096,1024] x [1024,1024]^T
        dim3 grid(DIM / 128, SEQ / 128);
        gemm_tf32_nt<<<grid, 256>>>(y_p, w_proj, out, SEQ, DIM, DIM);
    }
}